// round 3
// baseline (speedup 1.0000x reference)
#include <cuda_runtime.h>
#include <cuda_bf16.h>

// Problem constants (fixed by the reference)
#define NN     50000
#define EE     800000
#define F_IN   128
#define F_HID  256
#define F_OUT  128

// Scratch (allocation-free rule: __device__ globals; referenced ONLY in device code)
__device__ float g_deg [NN];
__device__ float g_dinv[NN];
__device__ float g_h1  [(size_t)NN * F_HID];   // x @ W1
__device__ float g_a1  [(size_t)NN * F_HID];   // aggregated layer1 (bias+relu in place)
__device__ float g_h2  [(size_t)NN * F_OUT];   // a1 @ W2

// ---------------------------------------------------------------------------
// Degree / normalization
// ---------------------------------------------------------------------------
__global__ void deg_init_k() {
    int i = blockIdx.x * blockDim.x + threadIdx.x;
    if (i < NN) g_deg[i] = 1.0f;   // self-loop
}

__global__ void deg_edges_k(const int* __restrict__ dst) {
    int e = blockIdx.x * blockDim.x + threadIdx.x;
    if (e < EE) atomicAdd(&g_deg[dst[e]], 1.0f);
}

__global__ void dinv_k() {
    int i = blockIdx.x * blockDim.x + threadIdx.x;
    if (i < NN) g_dinv[i] = rsqrtf(g_deg[i]);   // deg >= 1 always
}

// ---------------------------------------------------------------------------
// fp32 smem-tiled GEMM: C[M,Nc] = A[M,K] @ B[K,Nc]
// BM=BN=64, BK=16, 256 threads, 4x4 per thread.
// STAGE 1: A = x (param), C = g_h1.   STAGE 2: A = g_a1, C = g_h2.
// ---------------------------------------------------------------------------
template <int STAGE>
__global__ void gemm64_k(const float* __restrict__ Aext, const float* __restrict__ B,
                         int M, int Nc, int K) {
    const float* __restrict__ A = (STAGE == 1) ? Aext : (const float*)g_a1;
    float* __restrict__ C       = (STAGE == 1) ? g_h1 : g_h2;

    __shared__ float As[16][64];
    __shared__ float Bs[16][64];
    const int tid = threadIdx.x;
    const int tx = tid & 15, ty = tid >> 4;
    const int bm = blockIdx.y * 64, bn = blockIdx.x * 64;

    float acc[4][4] = {};

    for (int k0 = 0; k0 < K; k0 += 16) {
        {   // A tile 64x16
            int am = tid >> 2;
            int ak0 = (tid & 3) * 4;
            int gr = bm + am;
            #pragma unroll
            for (int i = 0; i < 4; i++) {
                int ak = ak0 + i;
                As[ak][am] = (gr < M) ? A[(size_t)gr * K + k0 + ak] : 0.0f;
            }
        }
        {   // B tile 16x64
            int bk = tid >> 4;
            int bb0 = (tid & 15) * 4;
            const float* brow = B + (size_t)(k0 + bk) * Nc + bn;
            #pragma unroll
            for (int i = 0; i < 4; i++)
                Bs[bk][bb0 + i] = brow[bb0 + i];
        }
        __syncthreads();

        #pragma unroll
        for (int kk = 0; kk < 16; kk++) {
            float ra[4], rb[4];
            #pragma unroll
            for (int i = 0; i < 4; i++) ra[i] = As[kk][ty * 4 + i];
            #pragma unroll
            for (int j = 0; j < 4; j++) rb[j] = Bs[kk][tx * 4 + j];
            #pragma unroll
            for (int i = 0; i < 4; i++)
                #pragma unroll
                for (int j = 0; j < 4; j++)
                    acc[i][j] += ra[i] * rb[j];
        }
        __syncthreads();
    }

    #pragma unroll
    for (int i = 0; i < 4; i++) {
        int gr = bm + ty * 4 + i;
        if (gr < M) {
            float* crow = C + (size_t)gr * Nc + bn + tx * 4;
            #pragma unroll
            for (int j = 0; j < 4; j++) crow[j] = acc[i][j];
        }
    }
}

// ---------------------------------------------------------------------------
// out[i,:] = dinv[i]^2 * h[i,:]   (self-loop term; initializes out buffer)
// STAGE 1: h=g_h1, out=g_a1.  STAGE 2: h=g_h2, out=param (d_out).
// ---------------------------------------------------------------------------
template <int STAGE, int F>
__global__ void selfloop_init_k(float* __restrict__ oext) {
    const float* __restrict__ h = (STAGE == 1) ? g_h1 : g_h2;
    float* __restrict__ out     = (STAGE == 1) ? g_a1 : oext;
    int idx = blockIdx.x * blockDim.x + threadIdx.x;
    if (idx < NN * F) {
        int i = idx / F;
        float d = g_dinv[i];
        out[idx] = d * d * h[idx];
    }
}

// ---------------------------------------------------------------------------
// Edge scatter: out[dst,:] += dinv[src]*dinv[dst] * h[src,:]. One warp / edge.
// ---------------------------------------------------------------------------
template <int STAGE, int F>
__global__ void scatter_edges_k(float* __restrict__ oext,
                                const int* __restrict__ src,
                                const int* __restrict__ dst) {
    const float* __restrict__ h = (STAGE == 1) ? g_h1 : g_h2;
    float* __restrict__ out     = (STAGE == 1) ? g_a1 : oext;
    int warp = (int)((blockIdx.x * (long long)blockDim.x + threadIdx.x) >> 5);
    int lane = threadIdx.x & 31;
    if (warp >= EE) return;
    int s = src[warp];
    int d = dst[warp];
    float norm = g_dinv[s] * g_dinv[d];
    const float* hs = h + (size_t)s * F;
    float* od = out + (size_t)d * F;
    #pragma unroll
    for (int f = lane; f < F; f += 32)
        atomicAdd(&od[f], hs[f] * norm);
}

// ---------------------------------------------------------------------------
// x = relu(x + b)
// ---------------------------------------------------------------------------
template <int STAGE, int F>
__global__ void bias_relu_k(float* __restrict__ oext, const float* __restrict__ b) {
    float* __restrict__ x = (STAGE == 1) ? g_a1 : oext;
    int idx = blockIdx.x * blockDim.x + threadIdx.x;
    if (idx < NN * F) {
        float v = x[idx] + b[idx & (F - 1)];
        x[idx] = v > 0.0f ? v : 0.0f;
    }
}

// ---------------------------------------------------------------------------
extern "C" void kernel_launch(void* const* d_in, const int* in_sizes, int n_in,
                              void* d_out, int out_size) {
    const float* x  = (const float*)d_in[0];
    const int*   ei = (const int*)d_in[1];   // [2, E] — JAX default x64-disabled => int32
    const float* W1 = (const float*)d_in[2];
    const float* b1 = (const float*)d_in[3];
    const float* W2 = (const float*)d_in[4];
    const float* b2 = (const float*)d_in[5];
    float*       out = (float*)d_out;

    const int* src = ei;
    const int* dst = ei + EE;

    const int T = 256;

    // degrees + normalization
    deg_init_k <<<(NN + T - 1) / T, T>>>();
    deg_edges_k<<<(EE + T - 1) / T, T>>>(dst);
    dinv_k     <<<(NN + T - 1) / T, T>>>();

    const int MB = (NN + 63) / 64;   // 782

    // ---- Layer 1 ----
    gemm64_k<1><<<dim3(F_HID / 64, MB), T>>>(x, W1, NN, F_HID, F_IN);
    selfloop_init_k<1, F_HID><<<(NN * F_HID + T - 1) / T, T>>>(out);
    scatter_edges_k<1, F_HID><<<(int)(((long long)EE * 32 + T - 1) / T), T>>>(out, src, dst);
    bias_relu_k<1, F_HID><<<(NN * F_HID + T - 1) / T, T>>>(out, b1);

    // ---- Layer 2 ----
    gemm64_k<2><<<dim3(F_OUT / 64, MB), T>>>(nullptr, W2, NN, F_OUT, F_HID);
    selfloop_init_k<2, F_OUT><<<(NN * F_OUT + T - 1) / T, T>>>(out);
    scatter_edges_k<2, F_OUT><<<(int)(((long long)EE * 32 + T - 1) / T), T>>>(out, src, dst);
    bias_relu_k<2, F_OUT><<<(NN * F_OUT + T - 1) / T, T>>>(out, b2);
}

// round 4
// speedup vs baseline: 1.2999x; 1.2999x over previous
#include <cuda_runtime.h>
#include <cuda_bf16.h>

#define NN     50000
#define EE     800000
#define F_IN   128
#define F_HID  256
#define F_OUT  128

// Scratch (__device__ globals; never materialized as host pointers)
__device__ int   g_cnt     [NN];
__device__ int   g_rowstart[NN + 1];
__device__ int   g_cursor  [NN];
__device__ int   g_adj     [EE];
__device__ float g_dinv    [NN];
__device__ float g_h1      [(size_t)NN * F_HID];   // x @ W1
__device__ float g_a1      [(size_t)NN * F_HID];   // aggregated+relu layer1
__device__ float g_h2      [(size_t)NN * F_OUT];   // a1 @ W2

// ---------------------------------------------------------------------------
// CSR build
// ---------------------------------------------------------------------------
__global__ void zero_cnt_k() {
    int i = blockIdx.x * blockDim.x + threadIdx.x;
    if (i < NN) g_cnt[i] = 0;
}

__global__ void cnt_k(const int* __restrict__ dst) {
    int e = blockIdx.x * blockDim.x + threadIdx.x;
    if (e < EE) atomicAdd(&g_cnt[dst[e]], 1);
}

__global__ void dinv_k() {
    int i = blockIdx.x * blockDim.x + threadIdx.x;
    if (i < NN) g_dinv[i] = rsqrtf((float)g_cnt[i] + 1.0f);   // + self loop
}

// Single block, 1024 threads. Strip-based exclusive scan of g_cnt -> g_rowstart
// (also seeds g_cursor with the same values for the fill pass).
__global__ void scan_k() {
    const int STRIP = (NN + 1023) / 1024;   // 49
    int tid = threadIdx.x;
    int begin = tid * STRIP;
    int end   = begin + STRIP; if (end > NN) end = NN;

    int local = 0;
    for (int i = begin; i < end; i++) local += g_cnt[i];

    int lane = tid & 31, warp = tid >> 5;
    int incl = local;
    #pragma unroll
    for (int o = 1; o < 32; o <<= 1) {
        int t = __shfl_up_sync(0xFFFFFFFFu, incl, o);
        if (lane >= o) incl += t;
    }
    __shared__ int wsum[32];
    if (lane == 31) wsum[warp] = incl;
    __syncthreads();
    if (warp == 0) {
        int w = wsum[lane];
        #pragma unroll
        for (int o = 1; o < 32; o <<= 1) {
            int t = __shfl_up_sync(0xFFFFFFFFu, w, o);
            if (lane >= o) w += t;
        }
        wsum[lane] = w;
    }
    __syncthreads();
    int excl = incl - local + (warp ? wsum[warp - 1] : 0);

    int run = excl;
    for (int i = begin; i < end; i++) {
        int c = g_cnt[i];
        g_rowstart[i] = run;
        g_cursor[i]   = run;
        run += c;
    }
    if (tid == 1023) g_rowstart[NN] = excl;   // begin>NN for this thread => excl == total == EE
}

__global__ void fill_k(const int* __restrict__ src, const int* __restrict__ dst) {
    int e = blockIdx.x * blockDim.x + threadIdx.x;
    if (e < EE) {
        int p = atomicAdd(&g_cursor[dst[e]], 1);
        g_adj[p] = src[e];
    }
}

// ---------------------------------------------------------------------------
// fp32 smem-tiled GEMM, 64x64x16, 256 threads, 4x4/thread, float4 smem reads
// STAGE 1: A = x (param), C = g_h1.   STAGE 2: A = g_a1, C = g_h2.
// ---------------------------------------------------------------------------
template <int STAGE>
__global__ void gemm64_k(const float* __restrict__ Aext, const float* __restrict__ B,
                         int M, int Nc, int K) {
    const float* __restrict__ A = (STAGE == 1) ? Aext : (const float*)g_a1;
    float* __restrict__ C       = (STAGE == 1) ? g_h1 : g_h2;

    __shared__ float As[16][64];
    __shared__ float Bs[16][64];
    const int tid = threadIdx.x;
    const int tx = tid & 15, ty = tid >> 4;
    const int bm = blockIdx.y * 64, bn = blockIdx.x * 64;

    float acc[4][4] = {};

    for (int k0 = 0; k0 < K; k0 += 16) {
        {   // A tile 64x16
            int am  = tid >> 2;
            int ak0 = (tid & 3) * 4;
            int gr  = bm + am;
            const float4 a4 = (gr < M)
                ? *(const float4*)&A[(size_t)gr * K + k0 + ak0]
                : make_float4(0.f, 0.f, 0.f, 0.f);
            As[ak0 + 0][am] = a4.x;
            As[ak0 + 1][am] = a4.y;
            As[ak0 + 2][am] = a4.z;
            As[ak0 + 3][am] = a4.w;
        }
        {   // B tile 16x64
            int bk  = tid >> 4;
            int bb0 = (tid & 15) * 4;
            *(float4*)&Bs[bk][bb0] = *(const float4*)&B[(size_t)(k0 + bk) * Nc + bn + bb0];
        }
        __syncthreads();

        #pragma unroll
        for (int kk = 0; kk < 16; kk++) {
            float4 a4 = *(const float4*)&As[kk][ty * 4];
            float4 b4 = *(const float4*)&Bs[kk][tx * 4];
            float ra[4] = {a4.x, a4.y, a4.z, a4.w};
            float rb[4] = {b4.x, b4.y, b4.z, b4.w};
            #pragma unroll
            for (int i = 0; i < 4; i++)
                #pragma unroll
                for (int j = 0; j < 4; j++)
                    acc[i][j] += ra[i] * rb[j];
        }
        __syncthreads();
    }

    #pragma unroll
    for (int i = 0; i < 4; i++) {
        int gr = bm + ty * 4 + i;
        if (gr < M) {
            float4 v = make_float4(acc[i][0], acc[i][1], acc[i][2], acc[i][3]);
            *(float4*)&C[(size_t)gr * Nc + bn + tx * 4] = v;
        }
    }
}

// ---------------------------------------------------------------------------
// CSR gather + selfloop + bias + relu.  One block of F threads per node.
// out[d,f] = relu( dinv[d]*( sum_in dinv[s]*h[s,f] + dinv[d]*h[d,f] ) + b[f] )
// ---------------------------------------------------------------------------
template <int STAGE, int F>
__global__ void gather_k(float* __restrict__ oext, const float* __restrict__ b) {
    const float* __restrict__ h = (STAGE == 1) ? g_h1 : g_h2;
    float* __restrict__ out     = (STAGE == 1) ? g_a1 : oext;

    int d   = blockIdx.x;
    int tid = threadIdx.x;

    float di  = g_dinv[d];
    float acc = di * h[(size_t)d * F + tid];   // self-loop term (pre final di mult)

    int j   = g_rowstart[d];
    int end = g_rowstart[d + 1];
    int s_next = (j < end) ? g_adj[j] : 0;
    while (j < end) {
        int s = s_next;
        float w = g_dinv[s];
        j++;
        if (j < end) s_next = g_adj[j];
        acc += w * h[(size_t)s * F + tid];
    }

    float v = di * acc + b[tid];
    out[(size_t)d * F + tid] = fmaxf(v, 0.0f);
}

// ---------------------------------------------------------------------------
extern "C" void kernel_launch(void* const* d_in, const int* in_sizes, int n_in,
                              void* d_out, int out_size) {
    const float* x  = (const float*)d_in[0];
    const int*   ei = (const int*)d_in[1];   // [2, E] int32 (JAX x64 disabled)
    const float* W1 = (const float*)d_in[2];
    const float* b1 = (const float*)d_in[3];
    const float* W2 = (const float*)d_in[4];
    const float* b2 = (const float*)d_in[5];
    float*       out = (float*)d_out;

    const int* src = ei;
    const int* dst = ei + EE;

    const int T = 256;

    // CSR build + normalization
    zero_cnt_k<<<(NN + T - 1) / T, T>>>();
    cnt_k     <<<(EE + T - 1) / T, T>>>(dst);
    dinv_k    <<<(NN + T - 1) / T, T>>>();
    scan_k    <<<1, 1024>>>();
    fill_k    <<<(EE + T - 1) / T, T>>>(src, dst);

    const int MB = (NN + 63) / 64;   // 782

    // ---- Layer 1 ----
    gemm64_k<1><<<dim3(F_HID / 64, MB), T>>>(x, W1, NN, F_HID, F_IN);
    gather_k<1, F_HID><<<NN, F_HID>>>(out, b1);

    // ---- Layer 2 ----
    gemm64_k<2><<<dim3(F_OUT / 64, MB), T>>>(nullptr, W2, NN, F_OUT, F_HID);
    gather_k<2, F_OUT><<<NN, F_OUT>>>(out, b2);
}

// round 5
// speedup vs baseline: 2.0431x; 1.5717x over previous
#include <cuda_runtime.h>
#include <cuda_bf16.h>

#define NN     50000
#define EE     800000
#define F_IN   128
#define F_HID  256
#define F_OUT  128

#define SCAN_T   256
#define NSTRIP   ((NN + SCAN_T - 1) / SCAN_T)   // 196

// Scratch (__device__ globals; never materialized as host pointers)
__device__ __align__(16) int   g_cnt     [NN];
__device__ __align__(16) int   g_rowstart[NN + 1];
__device__ __align__(16) int   g_cursor  [NN];
__device__ __align__(16) int   g_adj     [EE];
__device__ __align__(16) int   g_ssum    [NSTRIP];
__device__ __align__(16) int   g_soff    [NSTRIP];
__device__ __align__(16) float g_dinv    [NN];
__device__ __align__(16) float g_h1      [(size_t)NN * F_HID];
__device__ __align__(16) float g_a1      [(size_t)NN * F_HID];
__device__ __align__(16) float g_h2      [(size_t)NN * F_OUT];

// ---------------------------------------------------------------------------
// CSR build
// ---------------------------------------------------------------------------
__global__ void zero_cnt_k() {
    int i = blockIdx.x * blockDim.x + threadIdx.x;
    if (i < NN) g_cnt[i] = 0;
}

__global__ void cnt_k(const int* __restrict__ dst) {
    int e = blockIdx.x * blockDim.x + threadIdx.x;
    if (e < EE) atomicAdd(&g_cnt[dst[e]], 1);
}

__global__ void dinv_k() {
    int i = blockIdx.x * blockDim.x + threadIdx.x;
    if (i < NN) g_dinv[i] = rsqrtf((float)g_cnt[i] + 1.0f);   // + self loop
}

// Phase A: per-strip sums (one block per 256-element strip)
__global__ void strip_sum_k() {
    __shared__ int sh[SCAN_T];
    int gid = blockIdx.x * SCAN_T + threadIdx.x;
    sh[threadIdx.x] = (gid < NN) ? g_cnt[gid] : 0;
    __syncthreads();
    for (int o = SCAN_T / 2; o > 0; o >>= 1) {
        if (threadIdx.x < o) sh[threadIdx.x] += sh[threadIdx.x + o];
        __syncthreads();
    }
    if (threadIdx.x == 0) g_ssum[blockIdx.x] = sh[0];
}

// Phase B: single-block exclusive scan of the 196 strip sums (256 threads)
__global__ void scan_strips_k() {
    int tid  = threadIdx.x;
    int lane = tid & 31, warp = tid >> 5;
    int v = (tid < NSTRIP) ? g_ssum[tid] : 0;
    int incl = v;
    #pragma unroll
    for (int o = 1; o < 32; o <<= 1) {
        int t = __shfl_up_sync(0xFFFFFFFFu, incl, o);
        if (lane >= o) incl += t;
    }
    __shared__ int wsum[8];
    if (lane == 31) wsum[warp] = incl;
    __syncthreads();
    if (warp == 0 && lane < 8) {
        int w = wsum[lane];
        #pragma unroll
        for (int o = 1; o < 8; o <<= 1) {
            int t = __shfl_up_sync(0xFFu, w, o);
            if (lane >= o) w += t;
        }
        wsum[lane] = w;
    }
    __syncthreads();
    int total_incl = incl + (warp ? wsum[warp - 1] : 0);
    if (tid < NSTRIP) g_soff[tid] = total_incl - v;
    if (tid == SCAN_T - 1) g_rowstart[NN] = total_incl;   // == EE
}

// Phase C: per-strip exclusive scan + global offset -> rowstart/cursor
__global__ void rowstart_k() {
    int tid  = threadIdx.x;
    int gid  = blockIdx.x * SCAN_T + tid;
    int lane = tid & 31, warp = tid >> 5;
    int v = (gid < NN) ? g_cnt[gid] : 0;
    int incl = v;
    #pragma unroll
    for (int o = 1; o < 32; o <<= 1) {
        int t = __shfl_up_sync(0xFFFFFFFFu, incl, o);
        if (lane >= o) incl += t;
    }
    __shared__ int wsum[8];
    if (lane == 31) wsum[warp] = incl;
    __syncthreads();
    if (warp == 0 && lane < 8) {
        int w = wsum[lane];
        #pragma unroll
        for (int o = 1; o < 8; o <<= 1) {
            int t = __shfl_up_sync(0xFFu, w, o);
            if (lane >= o) w += t;
        }
        wsum[lane] = w;
    }
    __syncthreads();
    int excl = incl - v + (warp ? wsum[warp - 1] : 0) + g_soff[blockIdx.x];
    if (gid < NN) {
        g_rowstart[gid] = excl;
        g_cursor[gid]   = excl;
    }
}

__global__ void fill_k(const int* __restrict__ src, const int* __restrict__ dst) {
    int e = blockIdx.x * blockDim.x + threadIdx.x;
    if (e < EE) {
        int p = atomicAdd(&g_cursor[dst[e]], 1);
        g_adj[p] = src[e];
    }
}

// ---------------------------------------------------------------------------
// fp32 smem-tiled GEMM, 64x64x16, 256 threads, 4x4/thread, float4 smem reads
// STAGE 1: A = x (param), C = g_h1.   STAGE 2: A = g_a1, C = g_h2.
// ---------------------------------------------------------------------------
template <int STAGE>
__global__ void gemm64_k(const float* __restrict__ Aext, const float* __restrict__ B,
                         int M, int Nc, int K) {
    const float* __restrict__ A = (STAGE == 1) ? Aext : (const float*)g_a1;
    float* __restrict__ C       = (STAGE == 1) ? g_h1 : g_h2;

    __shared__ float As[16][64];
    __shared__ float Bs[16][64];
    const int tid = threadIdx.x;
    const int tx = tid & 15, ty = tid >> 4;
    const int bm = blockIdx.y * 64, bn = blockIdx.x * 64;

    float acc[4][4] = {};

    for (int k0 = 0; k0 < K; k0 += 16) {
        {   // A tile 64x16
            int am  = tid >> 2;
            int ak0 = (tid & 3) * 4;
            int gr  = bm + am;
            const float4 a4 = (gr < M)
                ? *(const float4*)&A[(size_t)gr * K + k0 + ak0]
                : make_float4(0.f, 0.f, 0.f, 0.f);
            As[ak0 + 0][am] = a4.x;
            As[ak0 + 1][am] = a4.y;
            As[ak0 + 2][am] = a4.z;
            As[ak0 + 3][am] = a4.w;
        }
        {   // B tile 16x64
            int bk  = tid >> 4;
            int bb0 = (tid & 15) * 4;
            *(float4*)&Bs[bk][bb0] = *(const float4*)&B[(size_t)(k0 + bk) * Nc + bn + bb0];
        }
        __syncthreads();

        #pragma unroll
        for (int kk = 0; kk < 16; kk++) {
            float4 a4 = *(const float4*)&As[kk][ty * 4];
            float4 b4 = *(const float4*)&Bs[kk][tx * 4];
            float ra[4] = {a4.x, a4.y, a4.z, a4.w};
            float rb[4] = {b4.x, b4.y, b4.z, b4.w};
            #pragma unroll
            for (int i = 0; i < 4; i++)
                #pragma unroll
                for (int j = 0; j < 4; j++)
                    acc[i][j] += ra[i] * rb[j];
        }
        __syncthreads();
    }

    #pragma unroll
    for (int i = 0; i < 4; i++) {
        int gr = bm + ty * 4 + i;
        if (gr < M) {
            float4 v = make_float4(acc[i][0], acc[i][1], acc[i][2], acc[i][3]);
            *(float4*)&C[(size_t)gr * Nc + bn + tx * 4] = v;
        }
    }
}

// ---------------------------------------------------------------------------
// CSR gather + selfloop + bias + relu. One block of F/4 threads per node,
// float4 per thread.
// out[d,f] = relu( dinv[d]*( sum_in dinv[s]*h[s,f] + dinv[d]*h[d,f] ) + b[f] )
// ---------------------------------------------------------------------------
template <int STAGE, int F>
__global__ void gather_k(float* __restrict__ oext, const float* __restrict__ bias) {
    constexpr int FC = F / 4;
    const float4* __restrict__ h4 = (STAGE == 1) ? (const float4*)g_h1 : (const float4*)g_h2;
    float4* __restrict__ out4     = (STAGE == 1) ? (float4*)g_a1 : (float4*)oext;

    int d   = blockIdx.x;
    int t   = threadIdx.x;          // 0..FC-1

    float di = g_dinv[d];
    float4 hv = h4[(size_t)d * FC + t];
    float4 acc = make_float4(di * hv.x, di * hv.y, di * hv.z, di * hv.w);

    int j   = g_rowstart[d];
    int end = g_rowstart[d + 1];
    int s_next = (j < end) ? g_adj[j] : 0;
    while (j < end) {
        int s = s_next;
        float w = g_dinv[s];
        j++;
        if (j < end) s_next = g_adj[j];
        float4 hs = h4[(size_t)s * FC + t];
        acc.x += w * hs.x;
        acc.y += w * hs.y;
        acc.z += w * hs.z;
        acc.w += w * hs.w;
    }

    float4 b4 = ((const float4*)bias)[t];
    float4 v;
    v.x = fmaxf(di * acc.x + b4.x, 0.0f);
    v.y = fmaxf(di * acc.y + b4.y, 0.0f);
    v.z = fmaxf(di * acc.z + b4.z, 0.0f);
    v.w = fmaxf(di * acc.w + b4.w, 0.0f);
    out4[(size_t)d * FC + t] = v;
}

// ---------------------------------------------------------------------------
extern "C" void kernel_launch(void* const* d_in, const int* in_sizes, int n_in,
                              void* d_out, int out_size) {
    const float* x  = (const float*)d_in[0];
    const int*   ei = (const int*)d_in[1];   // [2, E] int32 (JAX x64 disabled)
    const float* W1 = (const float*)d_in[2];
    const float* b1 = (const float*)d_in[3];
    const float* W2 = (const float*)d_in[4];
    const float* b2 = (const float*)d_in[5];
    float*       out = (float*)d_out;

    const int* src = ei;
    const int* dst = ei + EE;

    const int T = 256;

    // CSR build + normalization (3-phase parallel scan)
    zero_cnt_k   <<<(NN + T - 1) / T, T>>>();
    cnt_k        <<<(EE + T - 1) / T, T>>>(dst);
    dinv_k       <<<(NN + T - 1) / T, T>>>();
    strip_sum_k  <<<NSTRIP, SCAN_T>>>();
    scan_strips_k<<<1, SCAN_T>>>();
    rowstart_k   <<<NSTRIP, SCAN_T>>>();
    fill_k       <<<(EE + T - 1) / T, T>>>(src, dst);

    const int MB = (NN + 63) / 64;   // 782

    // ---- Layer 1 ----
    gemm64_k<1><<<dim3(F_HID / 64, MB), T>>>(x, W1, NN, F_HID, F_IN);
    gather_k<1, F_HID><<<NN, F_HID / 4>>>(out, b1);

    // ---- Layer 2 ----
    gemm64_k<2><<<dim3(F_OUT / 64, MB), T>>>(nullptr, W2, NN, F_OUT, F_HID);
    gather_k<2, F_OUT><<<NN, F_OUT / 4>>>(out, b2);
}

// round 6
// speedup vs baseline: 2.5397x; 1.2431x over previous
#include <cuda_runtime.h>
#include <cuda_bf16.h>

#define NN     50000
#define EE     800000
#define F_IN   128
#define F_HID  256
#define F_OUT  128

#define SCAN_T   256
#define NSTRIP   ((NN + SCAN_T - 1) / SCAN_T)   // 196

// Scratch (__device__ globals; never materialized as host pointers)
__device__ __align__(16) int   g_cnt     [NN];
__device__ __align__(16) int   g_rowstart[NN + 1];
__device__ __align__(16) int   g_cursor  [NN];
__device__ __align__(16) int   g_adj     [EE];
__device__ __align__(16) int   g_ssum    [NSTRIP];
__device__ __align__(16) int   g_soff    [NSTRIP];
__device__ __align__(16) float g_dinv    [NN];
__device__ __align__(16) float g_agg1    [(size_t)NN * F_IN];    // A_norm @ x
__device__ __align__(16) float g_a1      [(size_t)NN * F_HID];   // relu(agg1 @ W1 + b1)
__device__ __align__(16) float g_h2      [(size_t)NN * F_OUT];   // a1 @ W2

// ---------------------------------------------------------------------------
// CSR build
// ---------------------------------------------------------------------------
__global__ void zero_cnt_k() {
    int i = blockIdx.x * blockDim.x + threadIdx.x;
    if (i < NN) g_cnt[i] = 0;
}

__global__ void cnt_k(const int* __restrict__ dst) {
    int e = blockIdx.x * blockDim.x + threadIdx.x;
    if (e < EE) atomicAdd(&g_cnt[dst[e]], 1);
}

__global__ void dinv_k() {
    int i = blockIdx.x * blockDim.x + threadIdx.x;
    if (i < NN) g_dinv[i] = rsqrtf((float)g_cnt[i] + 1.0f);   // + self loop
}

__global__ void strip_sum_k() {
    __shared__ int sh[SCAN_T];
    int gid = blockIdx.x * SCAN_T + threadIdx.x;
    sh[threadIdx.x] = (gid < NN) ? g_cnt[gid] : 0;
    __syncthreads();
    for (int o = SCAN_T / 2; o > 0; o >>= 1) {
        if (threadIdx.x < o) sh[threadIdx.x] += sh[threadIdx.x + o];
        __syncthreads();
    }
    if (threadIdx.x == 0) g_ssum[blockIdx.x] = sh[0];
}

__global__ void scan_strips_k() {
    int tid  = threadIdx.x;
    int lane = tid & 31, warp = tid >> 5;
    int v = (tid < NSTRIP) ? g_ssum[tid] : 0;
    int incl = v;
    #pragma unroll
    for (int o = 1; o < 32; o <<= 1) {
        int t = __shfl_up_sync(0xFFFFFFFFu, incl, o);
        if (lane >= o) incl += t;
    }
    __shared__ int wsum[8];
    if (lane == 31) wsum[warp] = incl;
    __syncthreads();
    if (warp == 0 && lane < 8) {
        int w = wsum[lane];
        #pragma unroll
        for (int o = 1; o < 8; o <<= 1) {
            int t = __shfl_up_sync(0xFFu, w, o);
            if (lane >= o) w += t;
        }
        wsum[lane] = w;
    }
    __syncthreads();
    int total_incl = incl + (warp ? wsum[warp - 1] : 0);
    if (tid < NSTRIP) g_soff[tid] = total_incl - v;
    if (tid == SCAN_T - 1) g_rowstart[NN] = total_incl;   // == EE
}

__global__ void rowstart_k() {
    int tid  = threadIdx.x;
    int gid  = blockIdx.x * SCAN_T + tid;
    int lane = tid & 31, warp = tid >> 5;
    int v = (gid < NN) ? g_cnt[gid] : 0;
    int incl = v;
    #pragma unroll
    for (int o = 1; o < 32; o <<= 1) {
        int t = __shfl_up_sync(0xFFFFFFFFu, incl, o);
        if (lane >= o) incl += t;
    }
    __shared__ int wsum[8];
    if (lane == 31) wsum[warp] = incl;
    __syncthreads();
    if (warp == 0 && lane < 8) {
        int w = wsum[lane];
        #pragma unroll
        for (int o = 1; o < 8; o <<= 1) {
            int t = __shfl_up_sync(0xFFu, w, o);
            if (lane >= o) w += t;
        }
        wsum[lane] = w;
    }
    __syncthreads();
    int excl = incl - v + (warp ? wsum[warp - 1] : 0) + g_soff[blockIdx.x];
    if (gid < NN) {
        g_rowstart[gid] = excl;
        g_cursor[gid]   = excl;
    }
}

__global__ void fill_k(const int* __restrict__ src, const int* __restrict__ dst) {
    int e = blockIdx.x * blockDim.x + threadIdx.x;
    if (e < EE) {
        int p = atomicAdd(&g_cursor[dst[e]], 1);
        g_adj[p] = src[e];
    }
}

// ---------------------------------------------------------------------------
// fp32 GEMM 128x128x16, 256 threads, 8x8/thread as 4 quads (conflict-free LDS).
// STAGE 1: A=g_agg1, C=g_a1, epilogue relu(.+bias).  Nc=256, K=128.
// STAGE 2: A=g_a1,  C=g_h2, plain.                   Nc=128, K=256.
// ---------------------------------------------------------------------------
template <int STAGE>
__global__ void __launch_bounds__(256) gemm128_k(const float* __restrict__ B,
                                                 const float* __restrict__ bias,
                                                 int M, int Nc, int K) {
    const float* __restrict__ A = (STAGE == 1) ? g_agg1 : g_a1;
    float* __restrict__ C       = (STAGE == 1) ? g_a1   : g_h2;

    __shared__ float As[16][128];
    __shared__ float Bs[16][128];

    const int tid = threadIdx.x;
    const int tx = tid & 15, ty = tid >> 4;          // 16x16 thread grid
    const int bm = blockIdx.y * 128, bn = blockIdx.x * 128;

    float acc[2][2][4][4] = {};   // [rowhalf][colhalf][i][j]

    for (int k0 = 0; k0 < K; k0 += 16) {
        {   // A tile 128x16: thread row tid>>1, cols (tid&1)*8 (two float4)
            int am = tid >> 1;
            int ak = (tid & 1) * 8;
            int gr = bm + am;
            float4 a0, a1;
            if (gr < M) {
                const float* ap = &A[(size_t)gr * K + k0 + ak];
                a0 = *(const float4*)ap;
                a1 = *(const float4*)(ap + 4);
            } else {
                a0 = a1 = make_float4(0.f, 0.f, 0.f, 0.f);
            }
            As[ak + 0][am] = a0.x; As[ak + 1][am] = a0.y;
            As[ak + 2][am] = a0.z; As[ak + 3][am] = a0.w;
            As[ak + 4][am] = a1.x; As[ak + 5][am] = a1.y;
            As[ak + 6][am] = a1.z; As[ak + 7][am] = a1.w;
        }
        {   // B tile 16x128: thread row tid>>4, cols (tid&15)*8 (two float4)
            int bk = tid >> 4;
            int bc = (tid & 15) * 8;
            const float* bp = &B[(size_t)(k0 + bk) * Nc + bn + bc];
            *(float4*)&Bs[bk][bc]     = *(const float4*)bp;
            *(float4*)&Bs[bk][bc + 4] = *(const float4*)(bp + 4);
        }
        __syncthreads();

        #pragma unroll
        for (int kk = 0; kk < 16; kk++) {
            float4 a0 = *(const float4*)&As[kk][ty * 4];
            float4 a1 = *(const float4*)&As[kk][64 + ty * 4];
            float4 b0 = *(const float4*)&Bs[kk][tx * 4];
            float4 b1 = *(const float4*)&Bs[kk][64 + tx * 4];
            float ra[2][4] = {{a0.x, a0.y, a0.z, a0.w}, {a1.x, a1.y, a1.z, a1.w}};
            float rb[2][4] = {{b0.x, b0.y, b0.z, b0.w}, {b1.x, b1.y, b1.z, b1.w}};
            #pragma unroll
            for (int rh = 0; rh < 2; rh++)
                #pragma unroll
                for (int ch = 0; ch < 2; ch++)
                    #pragma unroll
                    for (int i = 0; i < 4; i++)
                        #pragma unroll
                        for (int j = 0; j < 4; j++)
                            acc[rh][ch][i][j] += ra[rh][i] * rb[ch][j];
        }
        __syncthreads();
    }

    #pragma unroll
    for (int rh = 0; rh < 2; rh++) {
        #pragma unroll
        for (int i = 0; i < 4; i++) {
            int gr = bm + rh * 64 + ty * 4 + i;
            if (gr < M) {
                #pragma unroll
                for (int ch = 0; ch < 2; ch++) {
                    int gc = bn + ch * 64 + tx * 4;
                    float4 v = make_float4(acc[rh][ch][i][0], acc[rh][ch][i][1],
                                           acc[rh][ch][i][2], acc[rh][ch][i][3]);
                    if (STAGE == 1) {
                        const float4 bv = *(const float4*)&bias[gc];
                        v.x = fmaxf(v.x + bv.x, 0.f);
                        v.y = fmaxf(v.y + bv.y, 0.f);
                        v.z = fmaxf(v.z + bv.z, 0.f);
                        v.w = fmaxf(v.w + bv.w, 0.f);
                    }
                    *(float4*)&C[(size_t)gr * Nc + gc] = v;
                }
            }
        }
    }
}

// ---------------------------------------------------------------------------
// CSR gather (F=128, warp per node, 8 nodes/block).
// agg[d,f] = dinv[d]*( sum_in dinv[s]*h[s,f] + dinv[d]*h[d,f] )   [+bias,relu]
// STAGE 1: h = x (param), out = g_agg1, no bias/relu.
// STAGE 2: h = g_h2,      out = d_out,  bias+relu.
// ---------------------------------------------------------------------------
template <int STAGE>
__global__ void gather_k(const float* __restrict__ hext, float* __restrict__ oext,
                         const float* __restrict__ bias) {
    const float4* __restrict__ h4 = (STAGE == 1) ? (const float4*)hext : (const float4*)g_h2;
    float4* __restrict__ out4     = (STAGE == 1) ? (float4*)g_agg1 : (float4*)oext;

    int warp = (blockIdx.x << 3) | (threadIdx.x >> 5);
    int t    = threadIdx.x & 31;      // float4 lane, FC = 32
    if (warp >= NN) return;
    int d = warp;

    float di = g_dinv[d];
    float4 hv = h4[(size_t)d * 32 + t];
    float4 acc = make_float4(di * hv.x, di * hv.y, di * hv.z, di * hv.w);

    int j   = g_rowstart[d];
    int end = g_rowstart[d + 1];
    int s_next = (j < end) ? g_adj[j] : 0;
    while (j < end) {
        int s = s_next;
        float w = g_dinv[s];
        j++;
        if (j < end) s_next = g_adj[j];
        float4 hs = h4[(size_t)s * 32 + t];
        acc.x += w * hs.x;
        acc.y += w * hs.y;
        acc.z += w * hs.z;
        acc.w += w * hs.w;
    }

    float4 v;
    if (STAGE == 2) {
        float4 b4 = ((const float4*)bias)[t];
        v.x = fmaxf(di * acc.x + b4.x, 0.f);
        v.y = fmaxf(di * acc.y + b4.y, 0.f);
        v.z = fmaxf(di * acc.z + b4.z, 0.f);
        v.w = fmaxf(di * acc.w + b4.w, 0.f);
    } else {
        v = make_float4(di * acc.x, di * acc.y, di * acc.z, di * acc.w);
    }
    out4[(size_t)d * 32 + t] = v;
}

// ---------------------------------------------------------------------------
extern "C" void kernel_launch(void* const* d_in, const int* in_sizes, int n_in,
                              void* d_out, int out_size) {
    const float* x  = (const float*)d_in[0];
    const int*   ei = (const int*)d_in[1];   // [2, E] int32 (JAX x64 disabled)
    const float* W1 = (const float*)d_in[2];
    const float* b1 = (const float*)d_in[3];
    const float* W2 = (const float*)d_in[4];
    const float* b2 = (const float*)d_in[5];
    float*       out = (float*)d_out;

    const int* src = ei;
    const int* dst = ei + EE;

    const int T = 256;

    // CSR build + normalization
    zero_cnt_k   <<<(NN + T - 1) / T, T>>>();
    cnt_k        <<<(EE + T - 1) / T, T>>>(dst);
    dinv_k       <<<(NN + T - 1) / T, T>>>();
    strip_sum_k  <<<NSTRIP, SCAN_T>>>();
    scan_strips_k<<<1, SCAN_T>>>();
    rowstart_k   <<<NSTRIP, SCAN_T>>>();
    fill_k       <<<(EE + T - 1) / T, T>>>(src, dst);

    const int GB = (NN + 7) / 8;        // gather blocks (8 nodes each)
    const int MB = (NN + 127) / 128;    // 391 gemm row-blocks

    // ---- Layer 1:  a1 = relu( (A_norm @ x) @ W1 + b1 ) ----
    gather_k<1><<<GB, 256>>>(x, nullptr, nullptr);
    gemm128_k<1><<<dim3(F_HID / 128, MB), 256>>>(W1, b1, NN, F_HID, F_IN);

    // ---- Layer 2:  out = relu( A_norm @ (a1 @ W2) + b2 ) ----
    gemm128_k<2><<<dim3(F_OUT / 128, MB), 256>>>(W2, nullptr, NN, F_OUT, F_HID);
    gather_k<2><<<GB, 256>>>(nullptr, out, b2);
}

// round 10
// speedup vs baseline: 3.0458x; 1.1993x over previous
#include <cuda_runtime.h>
#include <cuda_bf16.h>
#include <cstdint>

#define NN     50000
#define EE     800000
#define F_IN   128
#define F_HID  256
#define F_OUT  128

#define SCAN_T   256
#define NSTRIP   ((NN + SCAN_T - 1) / SCAN_T)   // 196

// Scratch (__device__ globals; never materialized as host pointers)
__device__ __align__(16) int   g_cnt     [NN];
__device__ __align__(16) int   g_rowstart[NN + 1];
__device__ __align__(16) int   g_cursor  [NN];
__device__ __align__(16) int   g_adj     [EE];
__device__ __align__(16) int   g_ssum    [NSTRIP];
__device__ __align__(16) int   g_soff    [NSTRIP];
__device__ __align__(16) float g_dinv    [NN];
__device__ __align__(16) float g_agg1    [(size_t)NN * F_IN];    // A_norm @ x
__device__ __align__(16) float g_a1      [(size_t)NN * F_HID];   // relu(agg1 @ W1 + b1)
__device__ __align__(16) float g_h2      [(size_t)NN * F_OUT];   // a1 @ W2

// ---------------------------------------------------------------------------
// CSR build
// ---------------------------------------------------------------------------
__global__ void zero_cnt_k() {
    int i = blockIdx.x * blockDim.x + threadIdx.x;
    if (i < NN) g_cnt[i] = 0;
}

__global__ void cnt_k(const int* __restrict__ dst) {
    int e = blockIdx.x * blockDim.x + threadIdx.x;
    if (e < EE) atomicAdd(&g_cnt[dst[e]], 1);
}

__global__ void dinv_k() {
    int i = blockIdx.x * blockDim.x + threadIdx.x;
    if (i < NN) g_dinv[i] = rsqrtf((float)g_cnt[i] + 1.0f);   // + self loop
}

__global__ void strip_sum_k() {
    __shared__ int sh[SCAN_T];
    int gid = blockIdx.x * SCAN_T + threadIdx.x;
    sh[threadIdx.x] = (gid < NN) ? g_cnt[gid] : 0;
    __syncthreads();
    for (int o = SCAN_T / 2; o > 0; o >>= 1) {
        if (threadIdx.x < o) sh[threadIdx.x] += sh[threadIdx.x + o];
        __syncthreads();
    }
    if (threadIdx.x == 0) g_ssum[blockIdx.x] = sh[0];
}

__global__ void scan_strips_k() {
    int tid  = threadIdx.x;
    int lane = tid & 31, warp = tid >> 5;
    int v = (tid < NSTRIP) ? g_ssum[tid] : 0;
    int incl = v;
    #pragma unroll
    for (int o = 1; o < 32; o <<= 1) {
        int t = __shfl_up_sync(0xFFFFFFFFu, incl, o);
        if (lane >= o) incl += t;
    }
    __shared__ int wsum[8];
    if (lane == 31) wsum[warp] = incl;
    __syncthreads();
    if (warp == 0 && lane < 8) {
        int w = wsum[lane];
        #pragma unroll
        for (int o = 1; o < 8; o <<= 1) {
            int t = __shfl_up_sync(0xFFu, w, o);
            if (lane >= o) w += t;
        }
        wsum[lane] = w;
    }
    __syncthreads();
    int total_incl = incl + (warp ? wsum[warp - 1] : 0);
    if (tid < NSTRIP) g_soff[tid] = total_incl - v;
    if (tid == SCAN_T - 1) g_rowstart[NN] = total_incl;   // == EE
}

__global__ void rowstart_k() {
    int tid  = threadIdx.x;
    int gid  = blockIdx.x * SCAN_T + tid;
    int lane = tid & 31, warp = tid >> 5;
    int v = (gid < NN) ? g_cnt[gid] : 0;
    int incl = v;
    #pragma unroll
    for (int o = 1; o < 32; o <<= 1) {
        int t = __shfl_up_sync(0xFFFFFFFFu, incl, o);
        if (lane >= o) incl += t;
    }
    __shared__ int wsum[8];
    if (lane == 31) wsum[warp] = incl;
    __syncthreads();
    if (warp == 0 && lane < 8) {
        int w = wsum[lane];
        #pragma unroll
        for (int o = 1; o < 8; o <<= 1) {
            int t = __shfl_up_sync(0xFFu, w, o);
            if (lane >= o) w += t;
        }
        wsum[lane] = w;
    }
    __syncthreads();
    int excl = incl - v + (warp ? wsum[warp - 1] : 0) + g_soff[blockIdx.x];
    if (gid < NN) {
        g_rowstart[gid] = excl;
        g_cursor[gid]   = excl;
    }
}

__global__ void fill_k(const int* __restrict__ src, const int* __restrict__ dst) {
    int e = blockIdx.x * blockDim.x + threadIdx.x;
    if (e < EE) {
        int p = atomicAdd(&g_cursor[dst[e]], 1);
        g_adj[p] = src[e];
    }
}

// ---------------------------------------------------------------------------
// tf32 mma.sync GEMM: C[M,Nc] = A[M,K] @ W[K,Nc]
// BM=128, BN=128, BK=32. 256 threads = 8 warps (2 m x 4 n), warp tile 64x32.
// Operands staged in smem in mma-fragment order (converted to tf32 on load):
// mainloop does LDS.128 (A-frag) / LDS.64 (B-frag) only.
// STAGE 1: A=g_agg1, C=g_a1, Nc=256, K=128, epilogue relu(.+bias)
// STAGE 2: A=g_a1,   C=g_h2, Nc=128, K=256, plain
// ---------------------------------------------------------------------------
__device__ __forceinline__ uint32_t f2tf32(float f) {
    uint32_t u;
    asm("cvt.rna.tf32.f32 %0, %1;" : "=r"(u) : "f"(f));
    return u;
}

template <int STAGE>
__global__ void __launch_bounds__(256) gemm_mma_k(const float* __restrict__ W,
                                                  const float* __restrict__ bias) {
    constexpr int Nc  = (STAGE == 1) ? F_HID : F_OUT;   // 256 / 128
    constexpr int K   = (STAGE == 1) ? F_IN  : F_HID;   // 128 / 256
    constexpr int NKT = K / 32;

    const float* __restrict__ A = (STAGE == 1) ? g_agg1 : g_a1;
    float* __restrict__ C       = (STAGE == 1) ? g_a1   : g_h2;

    // fragment-order staging: Af[kstep][mtile][lane][4], Bf[kstep][ntile][lane][2]
    __shared__ uint32_t Af[4][8][32][4];    // 16 KB
    __shared__ uint32_t Bf[4][16][32][2];   // 16 KB

    const int tid  = threadIdx.x;
    const int wid  = tid >> 5;
    const int lane = tid & 31;
    const int warp_m = wid >> 2;            // 0..1  (64 rows)
    const int warp_n = wid & 3;             // 0..3  (32 cols)
    const int bm = blockIdx.y * 128;
    const int bn = blockIdx.x * 128;

    float c[4][4][4];                       // [mtile][ntile][reg]
    #pragma unroll
    for (int i = 0; i < 4; i++)
        #pragma unroll
        for (int j = 0; j < 4; j++)
            #pragma unroll
            for (int q = 0; q < 4; q++) c[i][j][q] = 0.f;

    // loader coordinates
    const int ar  = tid >> 1;               // A row 0..127
    const int akc = (tid & 1) * 16;         // A col base 0/16
    const int bkr = tid >> 3;               // B k-row 0..31
    const int bnb = (tid & 7) * 16;         // B n base

    for (int kt = 0; kt < NKT; kt++) {
        const int k0 = kt * 32;

        // ---- A tile -> fragment order ----
        {
            int gr = bm + ar;
            const float* ap = &A[(size_t)gr * K + k0 + akc];
            int mt = ar >> 4;
            int lb = (ar & 7) * 4;
            int shi = ((ar & 15) >= 8) ? 1 : 0;
            #pragma unroll
            for (int i = 0; i < 4; i++) {
                float4 v = (gr < NN) ? *(const float4*)(ap + 4 * i)
                                     : make_float4(0.f, 0.f, 0.f, 0.f);
                int kc = akc + 4 * i;
                int ks = kc >> 3;
                int aslot = ((kc & 7) >= 4 ? 2 : 0) + shi;
                Af[ks][mt][lb + 0][aslot] = f2tf32(v.x);
                Af[ks][mt][lb + 1][aslot] = f2tf32(v.y);
                Af[ks][mt][lb + 2][aslot] = f2tf32(v.z);
                Af[ks][mt][lb + 3][aslot] = f2tf32(v.w);
            }
        }
        // ---- B tile (W[k][n]) -> fragment order ----
        {
            const float* bp = &W[(size_t)(k0 + bkr) * Nc + bn + bnb];
            int ks  = bkr >> 3;
            int kk  = bkr & 7;
            int slot = kk >> 2;
            int kl  = kk & 3;
            #pragma unroll
            for (int i = 0; i < 4; i++) {
                float4 v = *(const float4*)(bp + 4 * i);
                int nb = bnb + 4 * i;
                int nt = nb >> 3;
                int nn = nb & 7;
                Bf[ks][nt][(nn + 0) * 4 + kl][slot] = f2tf32(v.x);
                Bf[ks][nt][(nn + 1) * 4 + kl][slot] = f2tf32(v.y);
                Bf[ks][nt][(nn + 2) * 4 + kl][slot] = f2tf32(v.z);
                Bf[ks][nt][(nn + 3) * 4 + kl][slot] = f2tf32(v.w);
            }
        }
        __syncthreads();

        #pragma unroll
        for (int ks = 0; ks < 4; ks++) {
            uint32_t a[4][4], b[4][2];
            #pragma unroll
            for (int mt = 0; mt < 4; mt++) {
                uint4 av = *(const uint4*)&Af[ks][warp_m * 4 + mt][lane][0];
                a[mt][0] = av.x; a[mt][1] = av.y; a[mt][2] = av.z; a[mt][3] = av.w;
            }
            #pragma unroll
            for (int nt = 0; nt < 4; nt++) {
                uint2 bv = *(const uint2*)&Bf[ks][warp_n * 4 + nt][lane][0];
                b[nt][0] = bv.x; b[nt][1] = bv.y;
            }
            #pragma unroll
            for (int mt = 0; mt < 4; mt++)
                #pragma unroll
                for (int nt = 0; nt < 4; nt++)
                    asm volatile(
                        "mma.sync.aligned.m16n8k8.row.col.f32.tf32.tf32.f32 "
                        "{%0,%1,%2,%3}, {%4,%5,%6,%7}, {%8,%9}, {%0,%1,%2,%3};"
                        : "+f"(c[mt][nt][0]), "+f"(c[mt][nt][1]),
                          "+f"(c[mt][nt][2]), "+f"(c[mt][nt][3])
                        : "r"(a[mt][0]), "r"(a[mt][1]), "r"(a[mt][2]), "r"(a[mt][3]),
                          "r"(b[nt][0]), "r"(b[nt][1]));
        }
        __syncthreads();
    }

    // ---- epilogue ----
    #pragma unroll
    for (int mt = 0; mt < 4; mt++) {
        int row0 = bm + warp_m * 64 + mt * 16 + (lane >> 2);
        #pragma unroll
        for (int nt = 0; nt < 4; nt++) {
            int col = bn + warp_n * 32 + nt * 8 + (lane & 3) * 2;
            float2 lo = make_float2(c[mt][nt][0], c[mt][nt][1]);
            float2 hi = make_float2(c[mt][nt][2], c[mt][nt][3]);
            if (STAGE == 1) {
                float2 bv = *(const float2*)&bias[col];
                lo.x = fmaxf(lo.x + bv.x, 0.f);  lo.y = fmaxf(lo.y + bv.y, 0.f);
                hi.x = fmaxf(hi.x + bv.x, 0.f);  hi.y = fmaxf(hi.y + bv.y, 0.f);
            }
            if (row0 < NN)     *(float2*)&C[(size_t)row0 * Nc + col]       = lo;
            if (row0 + 8 < NN) *(float2*)&C[(size_t)(row0 + 8) * Nc + col] = hi;
        }
    }
}

// ---------------------------------------------------------------------------
// CSR gather (F=128, warp per node, 8 nodes/block).
// STAGE 1: h = x (param), out = g_agg1, no bias/relu.
// STAGE 2: h = g_h2,      out = d_out,  bias+relu.
// ---------------------------------------------------------------------------
template <int STAGE>
__global__ void gather_k(const float* __restrict__ hext, float* __restrict__ oext,
                         const float* __restrict__ bias) {
    const float4* __restrict__ h4 = (STAGE == 1) ? (const float4*)hext : (const float4*)g_h2;
    float4* __restrict__ out4     = (STAGE == 1) ? (float4*)g_agg1 : (float4*)oext;

    int warp = (blockIdx.x << 3) | (threadIdx.x >> 5);
    int t    = threadIdx.x & 31;
    if (warp >= NN) return;
    int d = warp;

    float di = g_dinv[d];
    float4 hv = h4[(size_t)d * 32 + t];
    float4 acc = make_float4(di * hv.x, di * hv.y, di * hv.z, di * hv.w);

    int j   = g_rowstart[d];
    int end = g_rowstart[d + 1];
    int s_next = (j < end) ? g_adj[j] : 0;
    while (j < end) {
        int s = s_next;
        float w = g_dinv[s];
        j++;
        if (j < end) s_next = g_adj[j];
        float4 hs = h4[(size_t)s * 32 + t];
        acc.x += w * hs.x;
        acc.y += w * hs.y;
        acc.z += w * hs.z;
        acc.w += w * hs.w;
    }

    float4 v;
    if (STAGE == 2) {
        float4 b4 = ((const float4*)bias)[t];
        v.x = fmaxf(di * acc.x + b4.x, 0.f);
        v.y = fmaxf(di * acc.y + b4.y, 0.f);
        v.z = fmaxf(di * acc.z + b4.z, 0.f);
        v.w = fmaxf(di * acc.w + b4.w, 0.f);
    } else {
        v = make_float4(di * acc.x, di * acc.y, di * acc.z, di * acc.w);
    }
    out4[(size_t)d * 32 + t] = v;
}

// ---------------------------------------------------------------------------
extern "C" void kernel_launch(void* const* d_in, const int* in_sizes, int n_in,
                              void* d_out, int out_size) {
    const float* x  = (const float*)d_in[0];
    const int*   ei = (const int*)d_in[1];   // [2, E] int32 (JAX x64 disabled)
    const float* W1 = (const float*)d_in[2];
    const float* b1 = (const float*)d_in[3];
    const float* W2 = (const float*)d_in[4];
    const float* b2 = (const float*)d_in[5];
    float*       out = (float*)d_out;

    const int* src = ei;
    const int* dst = ei + EE;

    const int T = 256;

    // CSR build + normalization
    zero_cnt_k   <<<(NN + T - 1) / T, T>>>();
    cnt_k        <<<(EE + T - 1) / T, T>>>(dst);
    dinv_k       <<<(NN + T - 1) / T, T>>>();
    strip_sum_k  <<<NSTRIP, SCAN_T>>>();
    scan_strips_k<<<1, SCAN_T>>>();
    rowstart_k   <<<NSTRIP, SCAN_T>>>();
    fill_k       <<<(EE + T - 1) / T, T>>>(src, dst);

    const int GB = (NN + 7) / 8;          // gather blocks (8 nodes each)
    const int MB = (NN + 127) / 128;      // 391 gemm row-tiles

    // ---- Layer 1:  a1 = relu( (A_norm @ x) @ W1 + b1 ) ----
    gather_k<1><<<GB, 256>>>(x, nullptr, nullptr);
    gemm_mma_k<1><<<dim3(F_HID / 128, MB), 256>>>(W1, b1);

    // ---- Layer 2:  out = relu( A_norm @ (a1 @ W2) + b2 ) ----
    gemm_mma_k<2><<<dim3(F_OUT / 128, MB), 256>>>(W2, nullptr);
    gather_k<2><<<GB, 256>>>(nullptr, out, b2);
}

// round 11
// speedup vs baseline: 3.0741x; 1.0093x over previous
#include <cuda_runtime.h>
#include <cuda_bf16.h>
#include <cstdint>

#define NN     50000
#define EE     800000
#define F_IN   128
#define F_HID  256
#define F_OUT  128

#define SCAN_T   256
#define NSTRIP   ((NN + SCAN_T - 1) / SCAN_T)   // 196

// Scratch (__device__ globals; never materialized as host pointers)
__device__ __align__(16) int   g_cnt     [NN];
__device__ __align__(16) int   g_rowstart[NN + 1];
__device__ __align__(16) int   g_cursor  [NN];
__device__ __align__(16) int   g_adj     [EE];
__device__ __align__(16) int   g_ssum    [NSTRIP];
__device__ __align__(16) int   g_soff    [NSTRIP];
__device__ __align__(16) float g_dinv    [NN];
__device__ __align__(16) float g_agg1    [(size_t)NN * F_IN];    // A_norm @ x
__device__ __align__(16) float g_a1      [(size_t)NN * F_HID];   // relu(agg1 @ W1 + b1)
__device__ __align__(16) float g_h2      [(size_t)NN * F_OUT];   // a1 @ W2

// ---------------------------------------------------------------------------
// CSR build
// ---------------------------------------------------------------------------
__global__ void zero_cnt_k() {
    int i = blockIdx.x * blockDim.x + threadIdx.x;
    if (i < NN) g_cnt[i] = 0;
}

__global__ void cnt_k(const int* __restrict__ dst) {
    int e = blockIdx.x * blockDim.x + threadIdx.x;
    if (e < EE) atomicAdd(&g_cnt[dst[e]], 1);
}

__global__ void strip_sum_k() {
    __shared__ int sh[SCAN_T];
    int gid = blockIdx.x * SCAN_T + threadIdx.x;
    sh[threadIdx.x] = (gid < NN) ? g_cnt[gid] : 0;
    __syncthreads();
    for (int o = SCAN_T / 2; o > 0; o >>= 1) {
        if (threadIdx.x < o) sh[threadIdx.x] += sh[threadIdx.x + o];
        __syncthreads();
    }
    if (threadIdx.x == 0) g_ssum[blockIdx.x] = sh[0];
}

__global__ void scan_strips_k() {
    int tid  = threadIdx.x;
    int lane = tid & 31, warp = tid >> 5;
    int v = (tid < NSTRIP) ? g_ssum[tid] : 0;
    int incl = v;
    #pragma unroll
    for (int o = 1; o < 32; o <<= 1) {
        int t = __shfl_up_sync(0xFFFFFFFFu, incl, o);
        if (lane >= o) incl += t;
    }
    __shared__ int wsum[8];
    if (lane == 31) wsum[warp] = incl;
    __syncthreads();
    if (warp == 0 && lane < 8) {
        int w = wsum[lane];
        #pragma unroll
        for (int o = 1; o < 8; o <<= 1) {
            int t = __shfl_up_sync(0xFFu, w, o);
            if (lane >= o) w += t;
        }
        wsum[lane] = w;
    }
    __syncthreads();
    int total_incl = incl + (warp ? wsum[warp - 1] : 0);
    if (tid < NSTRIP) g_soff[tid] = total_incl - v;
    if (tid == SCAN_T - 1) g_rowstart[NN] = total_incl;   // == EE
}

// per-strip exclusive scan + global offset; also computes dinv
__global__ void rowstart_k() {
    int tid  = threadIdx.x;
    int gid  = blockIdx.x * SCAN_T + tid;
    int lane = tid & 31, warp = tid >> 5;
    int v = (gid < NN) ? g_cnt[gid] : 0;
    int incl = v;
    #pragma unroll
    for (int o = 1; o < 32; o <<= 1) {
        int t = __shfl_up_sync(0xFFFFFFFFu, incl, o);
        if (lane >= o) incl += t;
    }
    __shared__ int wsum[8];
    if (lane == 31) wsum[warp] = incl;
    __syncthreads();
    if (warp == 0 && lane < 8) {
        int w = wsum[lane];
        #pragma unroll
        for (int o = 1; o < 8; o <<= 1) {
            int t = __shfl_up_sync(0xFFu, w, o);
            if (lane >= o) w += t;
        }
        wsum[lane] = w;
    }
    __syncthreads();
    int excl = incl - v + (warp ? wsum[warp - 1] : 0) + g_soff[blockIdx.x];
    if (gid < NN) {
        g_rowstart[gid] = excl;
        g_cursor[gid]   = excl;
        g_dinv[gid]     = rsqrtf((float)v + 1.0f);   // + self loop
    }
}

__global__ void fill_k(const int* __restrict__ src, const int* __restrict__ dst) {
    int e = blockIdx.x * blockDim.x + threadIdx.x;
    if (e < EE) {
        int p = atomicAdd(&g_cursor[dst[e]], 1);
        g_adj[p] = src[e];
    }
}

// ---------------------------------------------------------------------------
// tf32 mma.sync GEMM, software-pipelined (2-stage smem double buffer).
// C[M,Nc] = A[M,K] @ W[K,Nc]; BM=128, BN=128, BK=32; 8 warps (2m x 4n).
// Per k-tile: STS(cur) -> sync -> LDG(next->regs) -> MMA(cur). One barrier/tile.
// STAGE 1: A=g_agg1, C=g_a1, Nc=256, K=128, epilogue relu(.+bias)
// STAGE 2: A=g_a1,   C=g_h2, Nc=128, K=256, plain
// ---------------------------------------------------------------------------
__device__ __forceinline__ uint32_t f2tf32(float f) {
    uint32_t u;
    asm("cvt.rna.tf32.f32 %0, %1;" : "=r"(u) : "f"(f));
    return u;
}

#define AF_IDX(ks, mt, lane, slot) ((((ks) * 8 + (mt)) * 32 + (lane)) * 4 + (slot))
#define BF_IDX(ks, nt, lane, slot) ((((ks) * 16 + (nt)) * 32 + (lane)) * 2 + (slot))
#define STAGE_U32 8192   // 4096 u32 Af + 4096 u32 Bf per stage

template <int STAGE>
__global__ void __launch_bounds__(256) gemm_mma_k(const float* __restrict__ W,
                                                  const float* __restrict__ bias) {
    constexpr int Nc  = (STAGE == 1) ? F_HID : F_OUT;   // 256 / 128
    constexpr int K   = (STAGE == 1) ? F_IN  : F_HID;   // 128 / 256
    constexpr int NKT = K / 32;

    const float* __restrict__ A = (STAGE == 1) ? g_agg1 : g_a1;
    float* __restrict__ C       = (STAGE == 1) ? g_a1   : g_h2;

    extern __shared__ uint32_t dsm[];   // 2 stages x (Af 16KB + Bf 16KB)

    const int tid  = threadIdx.x;
    const int wid  = tid >> 5;
    const int lane = tid & 31;
    const int warp_m = wid >> 2;            // 0..1  (64 rows)
    const int warp_n = wid & 3;             // 0..3  (32 cols)
    const int bm = blockIdx.y * 128;
    const int bn = blockIdx.x * 128;

    float c[4][4][4];
    #pragma unroll
    for (int i = 0; i < 4; i++)
        #pragma unroll
        for (int j = 0; j < 4; j++)
            #pragma unroll
            for (int q = 0; q < 4; q++) c[i][j][q] = 0.f;

    // loader coordinates
    const int ar  = tid >> 1;               // A row 0..127
    const int akc = (tid & 1) * 16;         // A col base 0/16
    const int bkr = tid >> 3;               // B k-row 0..31
    const int bnb = (tid & 7) * 16;         // B n base
    const int gr  = bm + ar;
    const bool arow_ok = (gr < NN);

    // precomputed staging indices (A)
    const int a_mt   = ar >> 4;
    const int a_lb   = (ar & 7) * 4;
    const int a_shi  = ((ar & 15) >= 8) ? 1 : 0;
    // (B)
    const int b_ks   = bkr >> 3;
    const int b_kk   = bkr & 7;
    const int b_slot = b_kk >> 2;
    const int b_kl   = b_kk & 3;

    float4 rA[4], rB[4];

    auto ldg_tile = [&](int kt) {
        const int k0 = kt * 32;
        const float* ap = &A[(size_t)gr * K + k0 + akc];
        #pragma unroll
        for (int i = 0; i < 4; i++)
            rA[i] = arow_ok ? *(const float4*)(ap + 4 * i)
                            : make_float4(0.f, 0.f, 0.f, 0.f);
        const float* bp = &W[(size_t)(k0 + bkr) * Nc + bn + bnb];
        #pragma unroll
        for (int i = 0; i < 4; i++)
            rB[i] = *(const float4*)(bp + 4 * i);
    };

    auto sts_tile = [&](uint32_t* buf) {
        uint32_t* Afb = buf;
        uint32_t* Bfb = buf + 4096;
        #pragma unroll
        for (int i = 0; i < 4; i++) {
            int kc = akc + 4 * i;
            int ks = kc >> 3;
            int aslot = ((kc & 7) >= 4 ? 2 : 0) + a_shi;
            Afb[AF_IDX(ks, a_mt, a_lb + 0, aslot)] = f2tf32(rA[i].x);
            Afb[AF_IDX(ks, a_mt, a_lb + 1, aslot)] = f2tf32(rA[i].y);
            Afb[AF_IDX(ks, a_mt, a_lb + 2, aslot)] = f2tf32(rA[i].z);
            Afb[AF_IDX(ks, a_mt, a_lb + 3, aslot)] = f2tf32(rA[i].w);
        }
        #pragma unroll
        for (int i = 0; i < 4; i++) {
            int nb = bnb + 4 * i;
            int nt = nb >> 3;
            int nn = nb & 7;
            Bfb[BF_IDX(b_ks, nt, (nn + 0) * 4 + b_kl, b_slot)] = f2tf32(rB[i].x);
            Bfb[BF_IDX(b_ks, nt, (nn + 1) * 4 + b_kl, b_slot)] = f2tf32(rB[i].y);
            Bfb[BF_IDX(b_ks, nt, (nn + 2) * 4 + b_kl, b_slot)] = f2tf32(rB[i].z);
            Bfb[BF_IDX(b_ks, nt, (nn + 3) * 4 + b_kl, b_slot)] = f2tf32(rB[i].w);
        }
    };

    ldg_tile(0);

    for (int kt = 0; kt < NKT; kt++) {
        uint32_t* buf = dsm + (kt & 1) * STAGE_U32;
        sts_tile(buf);
        __syncthreads();
        if (kt + 1 < NKT) ldg_tile(kt + 1);

        const uint32_t* Afb = buf;
        const uint32_t* Bfb = buf + 4096;
        #pragma unroll
        for (int ks = 0; ks < 4; ks++) {
            uint32_t a[4][4], b[4][2];
            #pragma unroll
            for (int mt = 0; mt < 4; mt++) {
                uint4 av = *(const uint4*)&Afb[AF_IDX(ks, warp_m * 4 + mt, lane, 0)];
                a[mt][0] = av.x; a[mt][1] = av.y; a[mt][2] = av.z; a[mt][3] = av.w;
            }
            #pragma unroll
            for (int nt = 0; nt < 4; nt++) {
                uint2 bv = *(const uint2*)&Bfb[BF_IDX(ks, warp_n * 4 + nt, lane, 0)];
                b[nt][0] = bv.x; b[nt][1] = bv.y;
            }
            #pragma unroll
            for (int mt = 0; mt < 4; mt++)
                #pragma unroll
                for (int nt = 0; nt < 4; nt++)
                    asm volatile(
                        "mma.sync.aligned.m16n8k8.row.col.f32.tf32.tf32.f32 "
                        "{%0,%1,%2,%3}, {%4,%5,%6,%7}, {%8,%9}, {%0,%1,%2,%3};"
                        : "+f"(c[mt][nt][0]), "+f"(c[mt][nt][1]),
                          "+f"(c[mt][nt][2]), "+f"(c[mt][nt][3])
                        : "r"(a[mt][0]), "r"(a[mt][1]), "r"(a[mt][2]), "r"(a[mt][3]),
                          "r"(b[nt][0]), "r"(b[nt][1]));
        }
    }

    // ---- epilogue ----
    #pragma unroll
    for (int mt = 0; mt < 4; mt++) {
        int row0 = bm + warp_m * 64 + mt * 16 + (lane >> 2);
        #pragma unroll
        for (int nt = 0; nt < 4; nt++) {
            int col = bn + warp_n * 32 + nt * 8 + (lane & 3) * 2;
            float2 lo = make_float2(c[mt][nt][0], c[mt][nt][1]);
            float2 hi = make_float2(c[mt][nt][2], c[mt][nt][3]);
            if (STAGE == 1) {
                float2 bv = *(const float2*)&bias[col];
                lo.x = fmaxf(lo.x + bv.x, 0.f);  lo.y = fmaxf(lo.y + bv.y, 0.f);
                hi.x = fmaxf(hi.x + bv.x, 0.f);  hi.y = fmaxf(hi.y + bv.y, 0.f);
            }
            if (row0 < NN)     *(float2*)&C[(size_t)row0 * Nc + col]       = lo;
            if (row0 + 8 < NN) *(float2*)&C[(size_t)(row0 + 8) * Nc + col] = hi;
        }
    }
}

// ---------------------------------------------------------------------------
// CSR gather (F=128, warp per node, 8 nodes/block).
// STAGE 1: h = x (param), out = g_agg1, no bias/relu.
// STAGE 2: h = g_h2,      out = d_out,  bias+relu.
// ---------------------------------------------------------------------------
template <int STAGE>
__global__ void gather_k(const float* __restrict__ hext, float* __restrict__ oext,
                         const float* __restrict__ bias) {
    const float4* __restrict__ h4 = (STAGE == 1) ? (const float4*)hext : (const float4*)g_h2;
    float4* __restrict__ out4     = (STAGE == 1) ? (float4*)g_agg1 : (float4*)oext;

    int warp = (blockIdx.x << 3) | (threadIdx.x >> 5);
    int t    = threadIdx.x & 31;
    if (warp >= NN) return;
    int d = warp;

    float di = g_dinv[d];
    float4 hv = h4[(size_t)d * 32 + t];
    float4 acc = make_float4(di * hv.x, di * hv.y, di * hv.z, di * hv.w);

    int j   = g_rowstart[d];
    int end = g_rowstart[d + 1];
    int s_next = (j < end) ? g_adj[j] : 0;
    while (j < end) {
        int s = s_next;
        float w = g_dinv[s];
        j++;
        if (j < end) s_next = g_adj[j];
        float4 hs = h4[(size_t)s * 32 + t];
        acc.x += w * hs.x;
        acc.y += w * hs.y;
        acc.z += w * hs.z;
        acc.w += w * hs.w;
    }

    float4 v;
    if (STAGE == 2) {
        float4 b4 = ((const float4*)bias)[t];
        v.x = fmaxf(di * acc.x + b4.x, 0.f);
        v.y = fmaxf(di * acc.y + b4.y, 0.f);
        v.z = fmaxf(di * acc.z + b4.z, 0.f);
        v.w = fmaxf(di * acc.w + b4.w, 0.f);
    } else {
        v = make_float4(di * acc.x, di * acc.y, di * acc.z, di * acc.w);
    }
    out4[(size_t)d * 32 + t] = v;
}

// ---------------------------------------------------------------------------
extern "C" void kernel_launch(void* const* d_in, const int* in_sizes, int n_in,
                              void* d_out, int out_size) {
    const float* x  = (const float*)d_in[0];
    const int*   ei = (const int*)d_in[1];   // [2, E] int32 (JAX x64 disabled)
    const float* W1 = (const float*)d_in[2];
    const float* b1 = (const float*)d_in[3];
    const float* W2 = (const float*)d_in[4];
    const float* b2 = (const float*)d_in[5];
    float*       out = (float*)d_out;

    const int* src = ei;
    const int* dst = ei + EE;

    const int T = 256;
    const int GEMM_SMEM = 2 * STAGE_U32 * 4;   // 65536 bytes

    static bool attr_done = false;
    if (!attr_done) {
        cudaFuncSetAttribute(gemm_mma_k<1>, cudaFuncAttributeMaxDynamicSharedMemorySize, GEMM_SMEM);
        cudaFuncSetAttribute(gemm_mma_k<2>, cudaFuncAttributeMaxDynamicSharedMemorySize, GEMM_SMEM);
        attr_done = true;
    }

    // CSR build + normalization
    zero_cnt_k   <<<(NN + T - 1) / T, T>>>();
    cnt_k        <<<(EE + T - 1) / T, T>>>(dst);
    strip_sum_k  <<<NSTRIP, SCAN_T>>>();
    scan_strips_k<<<1, SCAN_T>>>();
    rowstart_k   <<<NSTRIP, SCAN_T>>>();
    fill_k       <<<(EE + T - 1) / T, T>>>(src, dst);

    const int GB = (NN + 7) / 8;          // gather blocks (8 nodes each)
    const int MB = (NN + 127) / 128;      // 391 gemm row-tiles

    // ---- Layer 1:  a1 = relu( (A_norm @ x) @ W1 + b1 ) ----
    gather_k<1><<<GB, 256>>>(x, nullptr, nullptr);
    gemm_mma_k<1><<<dim3(F_HID / 128, MB), 256, GEMM_SMEM>>>(W1, b1);

    // ---- Layer 2:  out = relu( A_norm @ (a1 @ W2) + b2 ) ----
    gemm_mma_k<2><<<dim3(F_OUT / 128, MB), 256, GEMM_SMEM>>>(W2, nullptr);
    gather_k<2><<<GB, 256>>>(nullptr, out, b2);
}